// round 13
// baseline (speedup 1.0000x reference)
#include <cuda_runtime.h>

#define NFEAT 8192
#define PDIM 256
#define RDIM 512
#define MROWS 32
#define NROWS 2048   // M*A
#define NSTACKS 32
#define NS 4
#define KSPLIT 4
#define KCHUNK (RDIM / KSPLIT)   // 128

#define BM 64
#define BN 64
#define BK 32

typedef unsigned long long ull;
typedef unsigned int uint;

// scratch (static device globals; no allocation in kernel_launch)
__device__ float g_proj4[KSPLIT * NROWS * PDIM];   // split-K partial projections
__device__ int   g_cnt[NS];
__device__ int   g_list[NS * NROWS];
__device__ float g_partial[NROWS * 4];             // 4 stack-groups per (m,a)
__device__ int   g_done;

__device__ __forceinline__ ull pack2(float lo, float hi) {
    ull d;
    asm("mov.b64 %0, {%1, %2};" : "=l"(d) : "r"(__float_as_uint(lo)), "r"(__float_as_uint(hi)));
    return d;
}
__device__ __forceinline__ ull fma2(ull a, ull b, ull c) {
    ull d;
    asm("fma.rn.f32x2 %0, %1, %2, %3;" : "=l"(d) : "l"(a), "l"(b), "l"(c));
    return d;
}
__device__ __forceinline__ void unpack2(ull v, float& lo, float& hi) {
    unsigned int l, h;
    asm("mov.b64 {%0, %1}, %2;" : "=r"(l), "=r"(h) : "l"(v));
    lo = __uint_as_float(l); hi = __uint_as_float(h);
}

// fused init + classify: one block, smem counters. List order is atomic-order
// dependent but only selects which GEMM tile handles which row; each row's
// arithmetic and output slot are fixed, so final output bits are deterministic.
// Also resets g_done for this graph replay (stream-ordered before k_feat).
__global__ void k_classify(const int* __restrict__ charges) {
    __shared__ int scnt[NS];
    int t = threadIdx.x;
    if (t < NS) scnt[t] = 0;
    if (t == 0) g_done = 0;
    __syncthreads();
    for (int row = t; row < NROWS; row += 1024) {
        int s = charges[row];
        int pos = atomicAdd(&scnt[s], 1);
        g_list[s * NROWS + pos] = row;
    }
    __syncthreads();
    if (t < NS) g_cnt[t] = scnt[t];
}

// Charge-grouped split-K GEMM (exact 48.2-champion shape):
// g_proj4[kslice][row, :] = rep[row, k0:k0+128] @ reductors[charge(row)][k0:k0+128, :]
__global__ void __launch_bounds__(256)
k_gemm(const float* __restrict__ rep,
       const float* __restrict__ reductors) {
    int s = blockIdx.z;
    int cnt = g_cnt[s];
    int row0 = blockIdx.y * BM;
    if (row0 >= cnt) return;

    int ntile  = blockIdx.x & 3;
    int kslice = blockIdx.x >> 2;
    int k0 = kslice * KCHUNK;

    __shared__ __align__(16) float As[BK][BM];
    __shared__ __align__(16) float Bs[BK][BN];
    __shared__ int rowIdx[BM];

    int t  = threadIdx.x;
    int tx = t & 15;
    int ty = t >> 4;

    if (t < BM) {
        int gi = row0 + t;
        rowIdx[t] = (gi < cnt) ? g_list[s * NROWS + gi] : -1;
    }
    __syncthreads();

    ull acc2[4][2] = {};
    const float* redS = reductors + s * RDIM * PDIM + ntile * BN;

    for (int kb = k0; kb < k0 + KCHUNK; kb += BK) {
        #pragma unroll
        for (int i = 0; i < 2; i++) {
            int slot = t * 2 + i;
            int r  = slot >> 3;
            int kq = slot & 7;
            int grow = rowIdx[r];
            float4 v = make_float4(0.f, 0.f, 0.f, 0.f);
            if (grow >= 0)
                v = *(const float4*)(rep + grow * RDIM + kb + kq * 4);
            As[kq * 4 + 0][r] = v.x;
            As[kq * 4 + 1][r] = v.y;
            As[kq * 4 + 2][r] = v.z;
            As[kq * 4 + 3][r] = v.w;
        }
        #pragma unroll
        for (int i = 0; i < 2; i++) {
            int slot = t * 2 + i;
            int k  = slot >> 4;
            int cq = slot & 15;
            float4 v = *(const float4*)(redS + (kb + k) * PDIM + cq * 4);
            *(float4*)&Bs[k][cq * 4] = v;
        }
        __syncthreads();

        #pragma unroll
        for (int k = 0; k < BK; k++) {
            float4 a4 = *(const float4*)&As[k][ty * 4];
            float4 b4 = *(const float4*)&Bs[k][tx * 4];
            ull a01 = pack2(a4.x, a4.y);
            ull a23 = pack2(a4.z, a4.w);
            float bv[4] = {b4.x, b4.y, b4.z, b4.w};
            #pragma unroll
            for (int jj = 0; jj < 4; jj++) {
                ull bd = pack2(bv[jj], bv[jj]);
                acc2[jj][0] = fma2(a01, bd, acc2[jj][0]);
                acc2[jj][1] = fma2(a23, bd, acc2[jj][1]);
            }
        }
        __syncthreads();
    }

    float acc[4][4];
    #pragma unroll
    for (int jj = 0; jj < 4; jj++) {
        unpack2(acc2[jj][0], acc[0][jj], acc[1][jj]);
        unpack2(acc2[jj][1], acc[2][jj], acc[3][jj]);
    }

    float* outSlice = g_proj4 + kslice * (NROWS * PDIM);
    #pragma unroll
    for (int ii = 0; ii < 4; ii++) {
        int r = rowIdx[ty * 4 + ii];
        if (r >= 0) {
            float4 v = make_float4(acc[ii][0], acc[ii][1], acc[ii][2], acc[ii][3]);
            *(float4*)(outSlice + r * PDIM + ntile * BN + tx * 4) = v;
        }
    }
}

// One warp per (pair, stack-group): 8192 tasks (exact champion shape).
// FWHT-256 with half-exchange lane stages: element (lane q, reg r) ends at
// logical index 128*(r>>2) + (q>>1)*8 + (q&1)*4 + (r&3); bias/alpha load at
// the matching permuted bases. Alpha-dot is permutation invariant.
// ONLY delta vs champion: fused final reduction via release-atomic counter +
// __ldcg reads in the single last block — no gpu-scope fence, so no
// CCTL.IVALL L1 poison for co-resident blocks (the R6 failure mode).
__global__ void __launch_bounds__(256)
k_feat(const int* __restrict__ charges,
       const float* __restrict__ Dmat,
       const float* __restrict__ bias,
       const float* __restrict__ alpha,
       float* __restrict__ out) {
    int warpId = threadIdx.x >> 5;
    int lane   = threadIdx.x & 31;
    int task   = blockIdx.x * 8 + warpId;   // 0..8191
    int pair   = task >> 2;
    int grp    = task & 3;
    int st0    = grp * 8;

    int s = charges[pair];

    uint projb[8];
    {
        const float* pp = g_proj4 + pair * PDIM + lane * 8;
        float4 p0 = *(const float4*)pp;
        float4 p1 = *(const float4*)(pp + 4);
        float acc[8] = {p0.x, p0.y, p0.z, p0.w, p1.x, p1.y, p1.z, p1.w};
        #pragma unroll
        for (int c = 1; c < KSPLIT; c++) {
            const float* pc = g_proj4 + c * (NROWS * PDIM) + pair * PDIM + lane * 8;
            float4 q0 = *(const float4*)pc;
            float4 q1 = *(const float4*)(pc + 4);
            acc[0] += q0.x; acc[1] += q0.y; acc[2] += q0.z; acc[3] += q0.w;
            acc[4] += q1.x; acc[5] += q1.y; acc[6] += q1.z; acc[7] += q1.w;
        }
        // fold FWHT normalization 1/16 (COEFF_NORM == 1 exactly)
        #pragma unroll
        for (int j = 0; j < 8; j++) projb[j] = __float_as_uint(acc[j] * 0.0625f);
    }

    const float* Ds = Dmat + s * NSTACKS * PDIM;
    const float* bs = bias + s * NFEAT;
    int pbase = ((lane >> 1) << 3) + ((lane & 1) << 2);

    float sum = 0.f;
    for (int st = st0; st < st0 + 8; st++) {
        const uint4* dp = (const uint4*)(Ds + st * PDIM + lane * 8);
        uint4 d0 = dp[0];
        uint4 d1 = dp[1];
        uint db[8] = {d0.x, d0.y, d0.z, d0.w, d1.x, d1.y, d1.z, d1.w};
        float v[8];
        #pragma unroll
        for (int j = 0; j < 8; j++)
            v[j] = __uint_as_float(projb[j] ^ (db[j] & 0x80000000u));

        float tv;
        tv = v[0]; v[0] = tv + v[1]; v[1] = tv - v[1];
        tv = v[2]; v[2] = tv + v[3]; v[3] = tv - v[3];
        tv = v[4]; v[4] = tv + v[5]; v[5] = tv - v[5];
        tv = v[6]; v[6] = tv + v[7]; v[7] = tv - v[7];

        tv = v[0]; v[0] = tv + v[2]; v[2] = tv - v[2];
        tv = v[1]; v[1] = tv + v[3]; v[3] = tv - v[3];
        tv = v[4]; v[4] = tv + v[6]; v[6] = tv - v[6];
        tv = v[5]; v[5] = tv + v[7]; v[7] = tv - v[7];

        tv = v[0]; v[0] = tv + v[4]; v[4] = tv - v[4];
        tv = v[1]; v[1] = tv + v[5]; v[5] = tv - v[5];
        tv = v[2]; v[2] = tv + v[6]; v[6] = tv - v[6];
        tv = v[3]; v[3] = tv + v[7]; v[7] = tv - v[7];

        #pragma unroll
        for (int msk = 1; msk <= 16; msk <<= 1) {
            bool hi = (lane & msk) != 0;
            float sgn = hi ? -1.f : 1.f;
            float nv[8];
            #pragma unroll
            for (int r = 0; r < 4; r++) {
                float send = hi ? v[r]     : v[r + 4];
                float keep = hi ? v[r + 4] : v[r];
                float recv = __shfl_xor_sync(0xffffffffu, send, msk);
                nv[r]     = keep + recv;
                nv[r + 4] = (keep - recv) * sgn;
            }
            #pragma unroll
            for (int r = 0; r < 8; r++) v[r] = nv[r];
        }

        const float* bp = bs + st * PDIM + pbase;
        const float* ap = alpha + st * PDIM + pbase;
        float4 b0 = *(const float4*)bp;
        float4 b1 = *(const float4*)(bp + 128);
        float4 a0 = *(const float4*)ap;
        float4 a1 = *(const float4*)(ap + 128);
        float bb[8] = {b0.x, b0.y, b0.z, b0.w, b1.x, b1.y, b1.z, b1.w};
        float aa[8] = {a0.x, a0.y, a0.z, a0.w, a1.x, a1.y, a1.z, a1.w};
        #pragma unroll
        for (int j = 0; j < 8; j++)
            sum += __cosf(v[j] + bb[j]) * aa[j];
    }

    #pragma unroll
    for (int off = 16; off; off >>= 1)
        sum += __shfl_down_sync(0xffffffffu, sum, off);
    if (lane == 0) g_partial[task] = sum;   // task = m*256 + a*4 + grp

    // ---- fused final reduction, fence-free ----
    // Producer side: release-atomic orders the g_partial stores at L2 without
    // touching L1 (no CCTL.IVALL). Consumer side: the last block reads
    // g_partial with __ldcg (L2-only), so no acquire-invalidate is needed.
    __shared__ int isLast;
    __syncthreads();   // all warp sums of this block stored
    if (threadIdx.x == 0) {
        int old;
        asm volatile("atom.release.gpu.global.add.s32 %0, [%1], 1;"
                     : "=r"(old) : "l"(&g_done) : "memory");
        isLast = (old == (int)gridDim.x - 1);
    }
    __syncthreads();
    if (isLast) {
        int t = threadIdx.x;            // 256 threads
        int m = t >> 3;
        int chunk = t & 7;
        const float* p = g_partial + m * 256 + chunk * 32;
        float v = 0.f;
        #pragma unroll
        for (int i = 0; i < 32; i++) v += __ldcg(p + i);
        #pragma unroll
        for (int off = 4; off; off >>= 1)
            v += __shfl_down_sync(0xffffffffu, v, off, 8);
        if (chunk == 0) out[m] = v * 0.015625f;   // FEAT_NORM = 1/64
    }
}

extern "C" void kernel_launch(void* const* d_in, const int* in_sizes, int n_in,
                              void* d_out, int out_size) {
    const float* rep       = (const float*)d_in[0];
    const int*   charges   = (const int*)d_in[1];
    const float* reductors = (const float*)d_in[2];
    const float* Dmat      = (const float*)d_in[3];
    const float* bias      = (const float*)d_in[4];
    const float* alpha     = (const float*)d_in[5];
    float* out = (float*)d_out;

    k_classify<<<1, 1024>>>(charges);
    dim3 gg(4 * KSPLIT, NROWS / BM, NS);   // (16, 32, 4); dead row-blocks exit fast
    k_gemm<<<gg, 256>>>(rep, reductors);
    k_feat<<<1024, 256>>>(charges, Dmat, bias, alpha, out);   // 8192 warps, fused reduce
}

// round 14
// speedup vs baseline: 1.0729x; 1.0729x over previous
#include <cuda_runtime.h>

#define NFEAT 8192
#define PDIM 256
#define RDIM 512
#define MROWS 32
#define NROWS 2048   // M*A
#define NSTACKS 32
#define NS 4
#define KSPLIT 4
#define KCHUNK (RDIM / KSPLIT)   // 128

#define BM 64
#define BN 64
#define BK 32

typedef unsigned long long ull;
typedef unsigned int uint;

// scratch (static device globals; no allocation in kernel_launch)
__device__ float g_proj4[KSPLIT * NROWS * PDIM];   // split-K partial projections
__device__ int   g_cnt[NS];
__device__ int   g_list[NS * NROWS];
__device__ float g_partial[NROWS * 4];             // 4 stack-groups per (m,a)

__device__ __forceinline__ ull pack2(float lo, float hi) {
    ull d;
    asm("mov.b64 %0, {%1, %2};" : "=l"(d) : "r"(__float_as_uint(lo)), "r"(__float_as_uint(hi)));
    return d;
}
__device__ __forceinline__ ull fma2(ull a, ull b, ull c) {
    ull d;
    asm("fma.rn.f32x2 %0, %1, %2, %3;" : "=l"(d) : "l"(a), "l"(b), "l"(c));
    return d;
}
__device__ __forceinline__ void unpack2(ull v, float& lo, float& hi) {
    unsigned int l, h;
    asm("mov.b64 {%0, %1}, %2;" : "=r"(l), "=r"(h) : "l"(v));
    lo = __uint_as_float(l); hi = __uint_as_float(h);
}

// fused init + classify: one block, smem counters (absorbs the DVFS ramp).
// List order is atomic-order dependent but only selects which GEMM tile
// handles which row; each row's arithmetic and output slot are fixed, so
// final output bits are deterministic.
__global__ void k_classify(const int* __restrict__ charges) {
    __shared__ int scnt[NS];
    int t = threadIdx.x;
    if (t < NS) scnt[t] = 0;
    __syncthreads();
    for (int row = t; row < NROWS; row += 1024) {
        int s = charges[row];
        int pos = atomicAdd(&scnt[s], 1);
        g_list[s * NROWS + pos] = row;
    }
    __syncthreads();
    if (t < NS) g_cnt[t] = scnt[t];
}

// Charge-grouped split-K GEMM (exact 48.2-champion shape):
// g_proj4[kslice][row, :] = rep[row, k0:k0+128] @ reductors[charge(row)][k0:k0+128, :]
__global__ void __launch_bounds__(256)
k_gemm(const float* __restrict__ rep,
       const float* __restrict__ reductors) {
    int s = blockIdx.z;
    int cnt = g_cnt[s];
    int row0 = blockIdx.y * BM;
    if (row0 >= cnt) return;

    int ntile  = blockIdx.x & 3;
    int kslice = blockIdx.x >> 2;
    int k0 = kslice * KCHUNK;

    __shared__ __align__(16) float As[BK][BM];
    __shared__ __align__(16) float Bs[BK][BN];
    __shared__ int rowIdx[BM];

    int t  = threadIdx.x;
    int tx = t & 15;
    int ty = t >> 4;

    if (t < BM) {
        int gi = row0 + t;
        rowIdx[t] = (gi < cnt) ? g_list[s * NROWS + gi] : -1;
    }
    __syncthreads();

    ull acc2[4][2] = {};
    const float* redS = reductors + s * RDIM * PDIM + ntile * BN;

    for (int kb = k0; kb < k0 + KCHUNK; kb += BK) {
        #pragma unroll
        for (int i = 0; i < 2; i++) {
            int slot = t * 2 + i;
            int r  = slot >> 3;
            int kq = slot & 7;
            int grow = rowIdx[r];
            float4 v = make_float4(0.f, 0.f, 0.f, 0.f);
            if (grow >= 0)
                v = *(const float4*)(rep + grow * RDIM + kb + kq * 4);
            As[kq * 4 + 0][r] = v.x;
            As[kq * 4 + 1][r] = v.y;
            As[kq * 4 + 2][r] = v.z;
            As[kq * 4 + 3][r] = v.w;
        }
        #pragma unroll
        for (int i = 0; i < 2; i++) {
            int slot = t * 2 + i;
            int k  = slot >> 4;
            int cq = slot & 15;
            float4 v = *(const float4*)(redS + (kb + k) * PDIM + cq * 4);
            *(float4*)&Bs[k][cq * 4] = v;
        }
        __syncthreads();

        #pragma unroll
        for (int k = 0; k < BK; k++) {
            float4 a4 = *(const float4*)&As[k][ty * 4];
            float4 b4 = *(const float4*)&Bs[k][tx * 4];
            ull a01 = pack2(a4.x, a4.y);
            ull a23 = pack2(a4.z, a4.w);
            float bv[4] = {b4.x, b4.y, b4.z, b4.w};
            #pragma unroll
            for (int jj = 0; jj < 4; jj++) {
                ull bd = pack2(bv[jj], bv[jj]);
                acc2[jj][0] = fma2(a01, bd, acc2[jj][0]);
                acc2[jj][1] = fma2(a23, bd, acc2[jj][1]);
            }
        }
        __syncthreads();
    }

    float acc[4][4];
    #pragma unroll
    for (int jj = 0; jj < 4; jj++) {
        unpack2(acc2[jj][0], acc[0][jj], acc[1][jj]);
        unpack2(acc2[jj][1], acc[2][jj], acc[3][jj]);
    }

    float* outSlice = g_proj4 + kslice * (NROWS * PDIM);
    #pragma unroll
    for (int ii = 0; ii < 4; ii++) {
        int r = rowIdx[ty * 4 + ii];
        if (r >= 0) {
            float4 v = make_float4(acc[ii][0], acc[ii][1], acc[ii][2], acc[ii][3]);
            *(float4*)(outSlice + r * PDIM + ntile * BN + tx * 4) = v;
        }
    }
}

// One warp per (pair, stack-group): 8192 tasks (exact champion shape).
// FWHT-256 with half-exchange lane stages: element (lane q, reg r) ends at
// logical index 128*(r>>2) + (q>>1)*8 + (q&1)*4 + (r&3); bias/alpha load at
// the matching permuted bases (two contiguous float4 runs; alpha-dot is
// permutation invariant).
// ONLY delta vs champion: g_proj4 is an 8 MB stream read exactly once ->
// __ldcg (L2-only) so it no longer evicts the REUSED Dmat/bias/alpha lines
// from L1 (k_feat's binding resource at ~68% L1).
__global__ void __launch_bounds__(256)
k_feat(const int* __restrict__ charges,
       const float* __restrict__ Dmat,
       const float* __restrict__ bias,
       const float* __restrict__ alpha) {
    int warpId = threadIdx.x >> 5;
    int lane   = threadIdx.x & 31;
    int task   = blockIdx.x * 8 + warpId;   // 0..8191
    int pair   = task >> 2;
    int grp    = task & 3;
    int st0    = grp * 8;

    int s = charges[pair];

    uint projb[8];
    {
        const float4* pp = (const float4*)(g_proj4 + pair * PDIM + lane * 8);
        float4 p0 = __ldcg(pp);
        float4 p1 = __ldcg(pp + 1);
        float acc[8] = {p0.x, p0.y, p0.z, p0.w, p1.x, p1.y, p1.z, p1.w};
        #pragma unroll
        for (int c = 1; c < KSPLIT; c++) {
            const float4* pc = (const float4*)(g_proj4 + c * (NROWS * PDIM) + pair * PDIM + lane * 8);
            float4 q0 = __ldcg(pc);
            float4 q1 = __ldcg(pc + 1);
            acc[0] += q0.x; acc[1] += q0.y; acc[2] += q0.z; acc[3] += q0.w;
            acc[4] += q1.x; acc[5] += q1.y; acc[6] += q1.z; acc[7] += q1.w;
        }
        // fold FWHT normalization 1/16 (COEFF_NORM == 1 exactly)
        #pragma unroll
        for (int j = 0; j < 8; j++) projb[j] = __float_as_uint(acc[j] * 0.0625f);
    }

    const float* Ds = Dmat + s * NSTACKS * PDIM;
    const float* bs = bias + s * NFEAT;
    int pbase = ((lane >> 1) << 3) + ((lane & 1) << 2);

    float sum = 0.f;
    for (int st = st0; st < st0 + 8; st++) {
        const uint4* dp = (const uint4*)(Ds + st * PDIM + lane * 8);
        uint4 d0 = dp[0];
        uint4 d1 = dp[1];
        uint db[8] = {d0.x, d0.y, d0.z, d0.w, d1.x, d1.y, d1.z, d1.w};
        float v[8];
        #pragma unroll
        for (int j = 0; j < 8; j++)
            v[j] = __uint_as_float(projb[j] ^ (db[j] & 0x80000000u));

        float tv;
        tv = v[0]; v[0] = tv + v[1]; v[1] = tv - v[1];
        tv = v[2]; v[2] = tv + v[3]; v[3] = tv - v[3];
        tv = v[4]; v[4] = tv + v[5]; v[5] = tv - v[5];
        tv = v[6]; v[6] = tv + v[7]; v[7] = tv - v[7];

        tv = v[0]; v[0] = tv + v[2]; v[2] = tv - v[2];
        tv = v[1]; v[1] = tv + v[3]; v[3] = tv - v[3];
        tv = v[4]; v[4] = tv + v[6]; v[6] = tv - v[6];
        tv = v[5]; v[5] = tv + v[7]; v[7] = tv - v[7];

        tv = v[0]; v[0] = tv + v[4]; v[4] = tv - v[4];
        tv = v[1]; v[1] = tv + v[5]; v[5] = tv - v[5];
        tv = v[2]; v[2] = tv + v[6]; v[6] = tv - v[6];
        tv = v[3]; v[3] = tv + v[7]; v[7] = tv - v[7];

        #pragma unroll
        for (int msk = 1; msk <= 16; msk <<= 1) {
            bool hi = (lane & msk) != 0;
            float sgn = hi ? -1.f : 1.f;
            float nv[8];
            #pragma unroll
            for (int r = 0; r < 4; r++) {
                float send = hi ? v[r]     : v[r + 4];
                float keep = hi ? v[r + 4] : v[r];
                float recv = __shfl_xor_sync(0xffffffffu, send, msk);
                nv[r]     = keep + recv;
                nv[r + 4] = (keep - recv) * sgn;
            }
            #pragma unroll
            for (int r = 0; r < 8; r++) v[r] = nv[r];
        }

        const float* bp = bs + st * PDIM + pbase;
        const float* ap = alpha + st * PDIM + pbase;
        float4 b0 = *(const float4*)bp;
        float4 b1 = *(const float4*)(bp + 128);
        float4 a0 = *(const float4*)ap;
        float4 a1 = *(const float4*)(ap + 128);
        float bb[8] = {b0.x, b0.y, b0.z, b0.w, b1.x, b1.y, b1.z, b1.w};
        float aa[8] = {a0.x, a0.y, a0.z, a0.w, a1.x, a1.y, a1.z, a1.w};
        #pragma unroll
        for (int j = 0; j < 8; j++)
            sum += __cosf(v[j] + bb[j]) * aa[j];
    }

    #pragma unroll
    for (int off = 16; off; off >>= 1)
        sum += __shfl_down_sync(0xffffffffu, sum, off);
    if (lane == 0) g_partial[task] = sum;   // task = m*256 + a*4 + grp
}

// out[m] = FEAT_NORM * sum over 256 contiguous partials
__global__ void k_reduce(float* __restrict__ out) {
    int m = blockIdx.x;
    int t = threadIdx.x;   // 256 threads
    float v = g_partial[m * 256 + t];
    #pragma unroll
    for (int off = 16; off; off >>= 1)
        v += __shfl_down_sync(0xffffffffu, v, off);
    __shared__ float sm8[8];
    if ((t & 31) == 0) sm8[t >> 5] = v;
    __syncthreads();
    if (t < 8) {
        float w = sm8[t];
        #pragma unroll
        for (int off = 4; off; off >>= 1)
            w += __shfl_down_sync(0xffu, w, off);
        if (t == 0) out[m] = 0.015625f * w;   // FEAT_NORM = 1/64
    }
}

extern "C" void kernel_launch(void* const* d_in, const int* in_sizes, int n_in,
                              void* d_out, int out_size) {
    const float* rep       = (const float*)d_in[0];
    const int*   charges   = (const int*)d_in[1];
    const float* reductors = (const float*)d_in[2];
    const float* Dmat      = (const float*)d_in[3];
    const float* bias      = (const float*)d_in[4];
    const float* alpha     = (const float*)d_in[5];
    float* out = (float*)d_out;

    k_classify<<<1, 1024>>>(charges);
    dim3 gg(4 * KSPLIT, NROWS / BM, NS);   // (16, 32, 4); dead row-blocks exit fast
    k_gemm<<<gg, 256>>>(rep, reductors);
    k_feat<<<1024, 256>>>(charges, Dmat, bias, alpha);   // 8192 warps
    k_reduce<<<MROWS, 256>>>(out);
}

// round 17
// speedup vs baseline: 1.0781x; 1.0048x over previous
#include <cuda_runtime.h>

#define NFEAT 8192
#define PDIM 256
#define RDIM 512
#define MROWS 32
#define NROWS 2048   // M*A
#define NSTACKS 32
#define NS 4
#define KSPLIT 4
#define KCHUNK (RDIM / KSPLIT)   // 128

#define BM 64
#define BK 16
#define NBLOCKS 148
#define NTHREADS 1024

typedef unsigned long long ull;
typedef unsigned int uint;

// scratch (static device globals; no allocation anywhere)
__device__ float g_proj4[KSPLIT * NROWS * PDIM];   // split-K partial projections
__device__ float g_partial[NROWS * 4];             // per (pair, stack-group) sums
__device__ int   g_bar;                            // grid barrier counter (reset at end)

__device__ __forceinline__ ull pack2(float lo, float hi) {
    ull d;
    asm("mov.b64 %0, {%1, %2};" : "=l"(d) : "r"(__float_as_uint(lo)), "r"(__float_as_uint(hi)));
    return d;
}
__device__ __forceinline__ ull fma2(ull a, ull b, ull c) {
    ull d;
    asm("fma.rn.f32x2 %0, %1, %2, %3;" : "=l"(d) : "l"(a), "l"(b), "l"(c));
    return d;
}
__device__ __forceinline__ void unpack2(ull v, float& lo, float& hi) {
    unsigned int l, h;
    asm("mov.b64 {%0, %1}, %2;" : "=r"(l), "=r"(h) : "l"(v));
    lo = __uint_as_float(l); hi = __uint_as_float(h);
}
// acquire spin: synchronizes-with producer __threadfence()+atomicAdd
__device__ __forceinline__ void bar_wait_acq(int target) {
    int v;
    do {
        asm volatile("ld.acquire.gpu.global.s32 %0, [%1];" : "=r"(v) : "l"(&g_bar) : "memory");
    } while (v < target);
}

__global__ void __launch_bounds__(NTHREADS, 1)
k_all(const float* __restrict__ rep,
      const int* __restrict__ charges,
      const float* __restrict__ reductors,
      const float* __restrict__ Dmat,
      const float* __restrict__ bias,
      const float* __restrict__ alpha,
      float* __restrict__ out) {
    __shared__ __align__(16) float As[BK][BM];       // 4 KB
    __shared__ __align__(16) float Bs[BK][PDIM];     // 16 KB
    __shared__ int rowIdx[BM];
    __shared__ int warpPfx[33];
    __shared__ int scnt[NS];

    int t    = threadIdx.x;
    int lane = t & 31;
    int w    = t >> 5;
    int b    = blockIdx.x;

    // ================= phase 0: charge counts (order-invariant sums) ========
    if (t < NS) scnt[t] = 0;
    __syncthreads();
    int c0 = charges[2 * t];
    int c1 = charges[2 * t + 1];
    atomicAdd(&scnt[c0], 1);
    atomicAdd(&scnt[c1], 1);
    __syncthreads();
    int cntS[NS];
    #pragma unroll
    for (int s = 0; s < NS; s++) cntS[s] = scnt[s];

    // task map: blkid = b>>2, kslice = b&3; blkid -> (s, rb) via nblk prefix
    int nb0 = (cntS[0] + BM - 1) / BM;
    int nb1 = (cntS[1] + BM - 1) / BM;
    int nb2 = (cntS[2] + BM - 1) / BM;
    int NB = nb0 + nb1 + nb2 + ((cntS[3] + BM - 1) / BM);   // <= 36 always
    int blkid  = b >> 2;
    int kslice = b & 3;

    if (blkid < NB) {
        int s, rb;
        if      (blkid < nb0)             { s = 0; rb = blkid; }
        else if (blkid < nb0 + nb1)       { s = 1; rb = blkid - nb0; }
        else if (blkid < nb0 + nb1 + nb2) { s = 2; rb = blkid - nb0 - nb1; }
        else                              { s = 3; rb = blkid - nb0 - nb1 - nb2; }
        int row0 = rb * BM;
        int k0   = kslice * KCHUNK;

        // ---- stable classification scan (deterministic): rows 2t, 2t+1 ----
        if (t < BM) rowIdx[t] = -1;
        uint mymask = (uint)(c0 == s) | ((uint)(c1 == s) << 1);
        int mycnt = __popc(mymask);
        int incl = mycnt;
        #pragma unroll
        for (int off = 1; off < 32; off <<= 1) {
            int n = __shfl_up_sync(0xffffffffu, incl, off);
            if (lane >= off) incl += n;
        }
        if (lane == 31) warpPfx[w + 1] = incl;
        __syncthreads();
        if (t == 0) {
            warpPfx[0] = 0;
            int run = 0;
            #pragma unroll
            for (int i = 1; i <= 32; i++) { run += warpPfx[i]; warpPfx[i] = run; }
        }
        __syncthreads();
        int rk = warpPfx[w] + incl - mycnt;
        if (mymask & 1u) {
            int loc = rk - row0;
            if (loc >= 0 && loc < BM) rowIdx[loc] = 2 * t;
            rk++;
        }
        if (mymask & 2u) {
            int loc = rk - row0;
            if (loc >= 0 && loc < BM) rowIdx[loc] = 2 * t + 1;
        }
        __syncthreads();

        // ---- GEMM: 64 x 256 x 128 tile, BK=16 ----
        int ty = t >> 6;        // 0..15 -> rows ty*4..ty*4+3
        int tx = t & 63;        // cols tx*4
        ull acc2[4][2] = {};
        const float* redS = reductors + s * RDIM * PDIM;

        for (int kb = k0; kb < k0 + KCHUNK; kb += BK) {
            if (t < 256) {
                int r  = t >> 2;       // tile row 0..63
                int kq = t & 3;        // float4 within BK=16
                int grow = rowIdx[r];
                float4 v = make_float4(0.f, 0.f, 0.f, 0.f);
                if (grow >= 0)
                    v = *(const float4*)(rep + grow * RDIM + kb + kq * 4);
                As[kq * 4 + 0][r] = v.x;
                As[kq * 4 + 1][r] = v.y;
                As[kq * 4 + 2][r] = v.z;
                As[kq * 4 + 3][r] = v.w;
            }
            {
                int k  = t >> 6;       // 0..15
                int cq = t & 63;       // float4 col group
                float4 v = *(const float4*)(redS + (kb + k) * PDIM + cq * 4);
                *(float4*)&Bs[k][cq * 4] = v;
            }
            __syncthreads();

            #pragma unroll
            for (int k = 0; k < BK; k++) {
                float4 a4 = *(const float4*)&As[k][ty * 4];
                float4 b4 = *(const float4*)&Bs[k][tx * 4];
                ull a01 = pack2(a4.x, a4.y);
                ull a23 = pack2(a4.z, a4.w);
                float bv[4] = {b4.x, b4.y, b4.z, b4.w};
                #pragma unroll
                for (int jj = 0; jj < 4; jj++) {
                    ull bd = pack2(bv[jj], bv[jj]);
                    acc2[jj][0] = fma2(a01, bd, acc2[jj][0]);
                    acc2[jj][1] = fma2(a23, bd, acc2[jj][1]);
                }
            }
            __syncthreads();
        }

        float acc[4][4];
        #pragma unroll
        for (int jj = 0; jj < 4; jj++) {
            unpack2(acc2[jj][0], acc[0][jj], acc[1][jj]);
            unpack2(acc2[jj][1], acc[2][jj], acc[3][jj]);
        }
        float* outSlice = g_proj4 + kslice * (NROWS * PDIM);
        #pragma unroll
        for (int ii = 0; ii < 4; ii++) {
            int r = rowIdx[ty * 4 + ii];
            if (r >= 0) {
                float4 v = make_float4(acc[ii][0], acc[ii][1], acc[ii][2], acc[ii][3]);
                __stcg((float4*)(outSlice + r * PDIM + tx * 4), v);   // straight to L2
            }
        }
    }

    // ================= grid barrier A (canonical fence pattern) =============
    __syncthreads();                       // all GEMM stores issued
    if (t == 0) {
        __threadfence();                   // publish this block's stores at gpu scope
        atomicAdd(&g_bar, 1);
        bar_wait_acq(NBLOCKS);             // acquire spin: syncs-with producers
    }
    __syncthreads();                       // extend visibility to all threads

    // ================= phase 2: feat (champion body, warp-stride) ===========
    for (int task = b * 32 + w; task < NROWS * 4; task += NBLOCKS * 32) {
        int pair = task >> 2;
        int grp  = task & 3;
        int st0  = grp * 8;
        int s = charges[pair];

        uint projb[8];
        {
            const float4* pp = (const float4*)(g_proj4 + pair * PDIM + lane * 8);
            float4 p0 = __ldcg(pp);
            float4 p1 = __ldcg(pp + 1);
            float accp[8] = {p0.x, p0.y, p0.z, p0.w, p1.x, p1.y, p1.z, p1.w};
            #pragma unroll
            for (int c = 1; c < KSPLIT; c++) {
                const float4* pc = (const float4*)(g_proj4 + c * (NROWS * PDIM) + pair * PDIM + lane * 8);
                float4 q0 = __ldcg(pc);
                float4 q1 = __ldcg(pc + 1);
                accp[0] += q0.x; accp[1] += q0.y; accp[2] += q0.z; accp[3] += q0.w;
                accp[4] += q1.x; accp[5] += q1.y; accp[6] += q1.z; accp[7] += q1.w;
            }
            // fold FWHT normalization 1/16 (COEFF_NORM == 1 exactly)
            #pragma unroll
            for (int j = 0; j < 8; j++) projb[j] = __float_as_uint(accp[j] * 0.0625f);
        }

        const float* Ds = Dmat + s * NSTACKS * PDIM;
        const float* bs = bias + s * NFEAT;
        int pbase = ((lane >> 1) << 3) + ((lane & 1) << 2);

        float sum = 0.f;
        for (int st = st0; st < st0 + 8; st++) {
            const uint4* dp = (const uint4*)(Ds + st * PDIM + lane * 8);
            uint4 d0 = dp[0];
            uint4 d1 = dp[1];
            uint db[8] = {d0.x, d0.y, d0.z, d0.w, d1.x, d1.y, d1.z, d1.w};
            float v[8];
            #pragma unroll
            for (int j = 0; j < 8; j++)
                v[j] = __uint_as_float(projb[j] ^ (db[j] & 0x80000000u));

            float tv;
            tv = v[0]; v[0] = tv + v[1]; v[1] = tv - v[1];
            tv = v[2]; v[2] = tv + v[3]; v[3] = tv - v[3];
            tv = v[4]; v[4] = tv + v[5]; v[5] = tv - v[5];
            tv = v[6]; v[6] = tv + v[7]; v[7] = tv - v[7];

            tv = v[0]; v[0] = tv + v[2]; v[2] = tv - v[2];
            tv = v[1]; v[1] = tv + v[3]; v[3] = tv - v[3];
            tv = v[4]; v[4] = tv + v[6]; v[6] = tv - v[6];
            tv = v[5]; v[5] = tv + v[7]; v[7] = tv - v[7];

            tv = v[0]; v[0] = tv + v[4]; v[4] = tv - v[4];
            tv = v[1]; v[1] = tv + v[5]; v[5] = tv - v[5];
            tv = v[2]; v[2] = tv + v[6]; v[6] = tv - v[6];
            tv = v[3]; v[3] = tv + v[7]; v[7] = tv - v[7];

            #pragma unroll
            for (int msk = 1; msk <= 16; msk <<= 1) {
                bool hi = (lane & msk) != 0;
                float sgn = hi ? -1.f : 1.f;
                float nv[8];
                #pragma unroll
                for (int r = 0; r < 4; r++) {
                    float send = hi ? v[r]     : v[r + 4];
                    float keep = hi ? v[r + 4] : v[r];
                    float recv = __shfl_xor_sync(0xffffffffu, send, msk);
                    nv[r]     = keep + recv;
                    nv[r + 4] = (keep - recv) * sgn;
                }
                #pragma unroll
                for (int r = 0; r < 8; r++) v[r] = nv[r];
            }

            const float* bp = bs + st * PDIM + pbase;
            const float* ap = alpha + st * PDIM + pbase;
            float4 b0 = *(const float4*)bp;
            float4 b1 = *(const float4*)(bp + 128);
            float4 a0 = *(const float4*)ap;
            float4 a1 = *(const float4*)(ap + 128);
            float bb[8] = {b0.x, b0.y, b0.z, b0.w, b1.x, b1.y, b1.z, b1.w};
            float aa[8] = {a0.x, a0.y, a0.z, a0.w, a1.x, a1.y, a1.z, a1.w};
            #pragma unroll
            for (int j = 0; j < 8; j++)
                sum += __cosf(v[j] + bb[j]) * aa[j];
        }

        #pragma unroll
        for (int off = 16; off; off >>= 1)
            sum += __shfl_down_sync(0xffffffffu, sum, off);
        if (lane == 0) __stcg(&g_partial[task], sum);   // task = m*256 + a*4 + grp
    }

    // ================= grid barrier B + fused reduce (block 0 only) =========
    __syncthreads();
    if (t == 0) {
        __threadfence();
        atomicAdd(&g_bar, 1);
        if (b == 0) bar_wait_acq(2 * NBLOCKS);   // only block 0 waits -> reset is safe
    }
    __syncthreads();
    if (b == 0) {
        if (t < 256) {
            int m = t >> 3;
            int chunk = t & 7;
            const float* p = g_partial + m * 256 + chunk * 32;
            float v = 0.f;
            #pragma unroll
            for (int i = 0; i < 32; i++) v += __ldcg(p + i);
            #pragma unroll
            for (int off = 4; off; off >>= 1)
                v += __shfl_down_sync(0xffffffffu, v, off, 8);
            if (chunk == 0) out[m] = v * 0.015625f;   // FEAT_NORM = 1/64
        }
        __syncthreads();
        if (t == 0) atomicExch(&g_bar, 0);   // reset for next graph replay
    }
}

extern "C" void kernel_launch(void* const* d_in, const int* in_sizes, int n_in,
                              void* d_out, int out_size) {
    const float* rep       = (const float*)d_in[0];
    const int*   charges   = (const int*)d_in[1];
    const float* reductors = (const float*)d_in[2];
    const float* Dmat      = (const float*)d_in[3];
    const float* bias      = (const float*)d_in[4];
    const float* alpha     = (const float*)d_in[5];
    float* out = (float*)d_out;

    k_all<<<NBLOCKS, NTHREADS>>>(rep, charges, reductors, Dmat, bias, alpha, out);
}